// round 8
// baseline (speedup 1.0000x reference)
#include <cuda_runtime.h>

#define NB 64
#define NP 1024
#define M1 128
#define M2 32

typedef unsigned long long ull;

#define PACKF2(d, lo, hi) asm("mov.b64 %0, {%1, %2};" : "=l"(d) : "f"(lo), "f"(hi))
#define UNPACKF2(lo, hi, d) asm("mov.b64 {%0, %1}, %2;" : "=f"(lo), "=f"(hi) : "l"(d))
#define FFMA2(acc, w, x) asm("fma.rn.f32x2 %0, %1, %2, %0;" : "+l"(acc) : "l"(w), "l"(x))

__device__ float g_bufA[(size_t)NB * 128 * M1 * 64];
__device__ float g_bufB[(size_t)NB * 128 * M1 * 64];
__device__ float g_f1[NB * 128 * M1];
__device__ float g_c1[NB * M1 * 3];
__device__ float g_c2[NB * M2 * 3];
__device__ int   g_i1[NB * M1];
__device__ int   g_i2[NB * M2];
__device__ int   g_n1[NB * M1 * 64];
__device__ int   g_n2[NB * M2 * 64];
__device__ float g_x3[NB * 259 * M2];
__device__ float g_z3a[NB * 512 * M2];
__device__ float g_z3b[NB * 256 * M2];
__device__ float g_xc[515 * NB];
__device__ float g_fa1[512 * NB];
__device__ float g_fa2[256 * NB];
__device__ __align__(16) float g_wt[350000];
__device__ float g_sum[512], g_sq[512];
__device__ float g_meanL[9][512], g_rstdL[9][512];
__device__ int   g_cnt;

__device__ __forceinline__ void finalize_block(int Cout, float invN, int slot,
                                               int gridTotal, int tid, int bdim) {
    __shared__ int s_last;
    __threadfence();
    __syncthreads();
    if (tid == 0) s_last = (atomicAdd(&g_cnt, 1) == gridTotal - 1) ? 1 : 0;
    __syncthreads();
    if (s_last) {
        for (int c = tid; c < Cout; c += bdim) {
            float s = __ldcg(&g_sum[c]), q = __ldcg(&g_sq[c]);
            float mn = s * invN;
            g_meanL[slot][c] = mn;
            g_rstdL[slot][c] = rsqrtf(q * invN - mn * mn + 1e-5f);
            g_sum[c] = 0.0f; g_sq[c] = 0.0f;
        }
        if (tid == 0) g_cnt = 0;
    }
}

__global__ void tw_all(const float* w1a, const float* w1b, const float* w1c,
                       const float* w2a, const float* w2b, const float* w2c,
                       const float* w3a, const float* w3b, const float* w3c) {
    const float* src[9] = { w1a, w1b, w1c, w2a, w2b, w2c, w3a, w3b, w3c };
    const int  O[9] = { 64, 64, 128, 128, 128, 256, 256, 256, 512 };
    const int  C[9] = { 3, 64, 64, 131, 128, 128, 259, 256, 256 };
    const int off[9] = { 0, 192, 4288, 12480, 29248, 45632, 78400, 144704, 210240 };
    int stride = gridDim.x * blockDim.x;
    int t0 = blockIdx.x * blockDim.x + threadIdx.x;
    for (int s = 0; s < 9; s++) {
        const float* W = src[s]; float* Wt = g_wt + off[s];
        int n = O[s] * C[s], Cs = C[s], Os = O[s];
        for (int i = t0; i < n; i += stride) {
            int o = i / Cs, c = i - o * Cs;
            Wt[c * Os + o] = W[i];
        }
    }
}

// ---- fused FPS(128) + ball-query for stage 1 ----
__global__ __launch_bounds__(1024) void fpsbq1_k(const float* __restrict__ coords) {
    __shared__ float sp[3 * NP];
    __shared__ float sv[32]; __shared__ int si[32];
    __shared__ float sc[3]; __shared__ int sfar;
    int b = blockIdx.x, t = threadIdx.x, lane = t & 31, w = t >> 5;
    const float* cb = coords + (size_t)b * 3 * NP;
    for (int i = t; i < 3 * NP; i += 1024) sp[i] = cb[i];
    __syncthreads();
    float px = sp[t], py = sp[NP + t], pz = sp[2 * NP + t];
    float dist = 1e10f; int far = 0;
    for (int s = 0; s < 128; s++) {
        if (t == far) {
            sc[0] = px; sc[1] = py; sc[2] = pz;
            g_i1[b * 128 + s] = far;
            float* cw = g_c1 + ((size_t)b * 128 + s) * 3;
            cw[0] = px; cw[1] = py; cw[2] = pz;
        }
        __syncthreads();
        float dx = __fadd_rn(px, -sc[0]), dy = __fadd_rn(py, -sc[1]), dz = __fadd_rn(pz, -sc[2]);
        float d = __fadd_rn(__fadd_rn(__fmul_rn(dx, dx), __fmul_rn(dy, dy)), __fmul_rn(dz, dz));
        dist = fminf(dist, d);
        float v = dist; int ii = t;
        #pragma unroll
        for (int o = 16; o; o >>= 1) {
            float ov = __shfl_down_sync(0xffffffffu, v, o);
            int oi = __shfl_down_sync(0xffffffffu, ii, o);
            if (ov > v || (ov == v && oi < ii)) { v = ov; ii = oi; }
        }
        if (lane == 0) { sv[w] = v; si[w] = ii; }
        __syncthreads();
        if (t < 32) {
            float v2 = sv[t]; int i2 = si[t];
            #pragma unroll
            for (int o = 16; o; o >>= 1) {
                float ov = __shfl_down_sync(0xffffffffu, v2, o);
                int oi = __shfl_down_sync(0xffffffffu, i2, o);
                if (ov > v2 || (ov == v2 && oi < i2)) { v2 = ov; i2 = oi; }
            }
            if (t == 0) sfar = i2;
        }
        __syncthreads();
        far = sfar;
    }
    __syncthreads();
    // ball query: warp handles 4 centers
    float r2 = (float)(0.2 * 0.2);
    for (int mi = 0; mi < 4; mi++) {
        int m = w * 4 + mi;
        const float* cr = g_c1 + ((size_t)b * 128 + m) * 3;
        float cx = cr[0], cy = cr[1], cz = cr[2];
        int base = (b * 128 + m) * 64, cnt = 0, firstj = -1;
        for (int ch = 0; ch < 32; ch++) {
            int j = (ch << 5) + lane;
            float dx = __fadd_rn(cx, -sp[j]);
            float dy = __fadd_rn(cy, -sp[NP + j]);
            float dz = __fadd_rn(cz, -sp[2 * NP + j]);
            float d = __fadd_rn(__fadd_rn(__fmul_rn(dx, dx), __fmul_rn(dy, dy)), __fmul_rn(dz, dz));
            bool hit = d < r2;
            unsigned mask = __ballot_sync(0xffffffffu, hit);
            int pos = cnt + __popc(mask & ((1u << lane) - 1u));
            if (hit && pos < 64) g_n1[base + pos] = j;
            if (firstj < 0 && mask) firstj = (ch << 5) + __ffs(mask) - 1;
            cnt += __popc(mask);
            if (cnt >= 64) break;
        }
        for (int s2 = cnt + lane; s2 < 64; s2 += 32) g_n1[base + s2] = firstj;
    }
}

// ---- fused FPS(32) + ball-query for stage 2 ----
__global__ __launch_bounds__(128) void fpsbq2_k() {
    __shared__ float sp[3 * 128];
    __shared__ float sv[4]; __shared__ int si[4];
    __shared__ float sc[3]; __shared__ int sfar;
    int b = blockIdx.x, t = threadIdx.x, lane = t & 31, w = t >> 5;
    for (int i = t; i < 384; i += 128) {
        int c = i >> 7, j = i & 127;
        sp[i] = g_c1[((size_t)b * 128 + j) * 3 + c];
    }
    __syncthreads();
    float px = sp[t], py = sp[128 + t], pz = sp[256 + t];
    float dist = 1e10f; int far = 0;
    for (int s = 0; s < 32; s++) {
        if (t == far) {
            sc[0] = px; sc[1] = py; sc[2] = pz;
            g_i2[b * 32 + s] = far;
            float* cw = g_c2 + ((size_t)b * 32 + s) * 3;
            cw[0] = px; cw[1] = py; cw[2] = pz;
        }
        __syncthreads();
        float dx = __fadd_rn(px, -sc[0]), dy = __fadd_rn(py, -sc[1]), dz = __fadd_rn(pz, -sc[2]);
        float d = __fadd_rn(__fadd_rn(__fmul_rn(dx, dx), __fmul_rn(dy, dy)), __fmul_rn(dz, dz));
        dist = fminf(dist, d);
        float v = dist; int ii = t;
        #pragma unroll
        for (int o = 16; o; o >>= 1) {
            float ov = __shfl_down_sync(0xffffffffu, v, o);
            int oi = __shfl_down_sync(0xffffffffu, ii, o);
            if (ov > v || (ov == v && oi < ii)) { v = ov; ii = oi; }
        }
        if (lane == 0) { sv[w] = v; si[w] = ii; }
        __syncthreads();
        if (t < 32) {
            float v2 = (t < 4) ? sv[t] : -1.0f;
            int i2 = (t < 4) ? si[t] : 0x7fffffff;
            #pragma unroll
            for (int o = 16; o; o >>= 1) {
                float ov = __shfl_down_sync(0xffffffffu, v2, o);
                int oi = __shfl_down_sync(0xffffffffu, i2, o);
                if (ov > v2 || (ov == v2 && oi < i2)) { v2 = ov; i2 = oi; }
            }
            if (t == 0) sfar = i2;
        }
        __syncthreads();
        far = sfar;
    }
    __syncthreads();
    float r2 = (float)(0.4 * 0.4);
    for (int mi = 0; mi < 8; mi++) {
        int m = w * 8 + mi;
        const float* cr = g_c2 + ((size_t)b * 32 + m) * 3;
        float cx = cr[0], cy = cr[1], cz = cr[2];
        int base = (b * 32 + m) * 64, cnt = 0, firstj = -1;
        for (int ch = 0; ch < 4; ch++) {
            int j = (ch << 5) + lane;
            float dx = __fadd_rn(cx, -sp[j]);
            float dy = __fadd_rn(cy, -sp[128 + j]);
            float dz = __fadd_rn(cz, -sp[256 + j]);
            float d = __fadd_rn(__fadd_rn(__fmul_rn(dx, dx), __fmul_rn(dy, dy)), __fmul_rn(dz, dz));
            bool hit = d < r2;
            unsigned mask = __ballot_sync(0xffffffffu, hit);
            int pos = cnt + __popc(mask & ((1u << lane) - 1u));
            if (hit && pos < 64) g_n2[base + pos] = j;
            if (firstj < 0 && mask) firstj = (ch << 5) + __ffs(mask) - 1;
            cnt += __popc(mask);
            if (cnt >= 64) break;
        }
        for (int s2 = cnt + lane; s2 < 64; s2 += 32) g_n2[base + s2] = firstj;
    }
}

// ---- stage-1 layer-1: fused gather + 3->64 conv, smem stats, finalize slot0 ----
__global__ __launch_bounds__(256) void convA_k(const float* __restrict__ coords,
                                               const float* __restrict__ w1a) {
    __shared__ float s_in[3 * 64];
    __shared__ float sW[3][64];
    __shared__ int sn[64];
    __shared__ float scx[3];
    __shared__ float sS[64], sQ[64];
    int bm = blockIdx.x, b = bm >> 7, m = bm & 127;
    int tid = threadIdx.x, lane = tid & 31, wp = tid >> 5;
    if (tid < 64) { sn[tid] = g_n1[bm * 64 + tid]; sS[tid] = 0.0f; sQ[tid] = 0.0f; }
    if (tid >= 64 && tid < 67) scx[tid - 64] = g_c1[((size_t)b * M1 + m) * 3 + (tid - 64)];
    if (tid >= 64 && tid < 256) {
        int i = tid - 64;
        if (i < 192) { int o = i / 3, c = i - o * 3; sW[c][o] = w1a[i]; }
    }
    __syncthreads();
    if (tid < 192) {
        int c = tid >> 6, k = tid & 63;
        s_in[c * 64 + k] = coords[(size_t)b * 3 * NP + c * NP + sn[k]] - scx[c];
    }
    __syncthreads();
    int ob = wp * 8;
    float a[8][2];
    #pragma unroll
    for (int j = 0; j < 8; j++) { a[j][0] = 0.0f; a[j][1] = 0.0f; }
    const float2* xrow = (const float2*)s_in + lane;
    #pragma unroll
    for (int c = 0; c < 3; c++) {
        float2 xv = xrow[c * 32];
        float4 w0 = *(const float4*)&sW[c][ob];
        float4 w1 = *(const float4*)&sW[c][ob + 4];
        float wv[8] = { w0.x, w0.y, w0.z, w0.w, w1.x, w1.y, w1.z, w1.w };
        #pragma unroll
        for (int j = 0; j < 8; j++) { a[j][0] += wv[j] * xv.x; a[j][1] += wv[j] * xv.y; }
    }
    size_t MK = (size_t)M1 * 64;
    float* outb = g_bufA + (size_t)b * 64 * MK + (size_t)m * 64;
    float ss[8], qq[8];
    #pragma unroll
    for (int j = 0; j < 8; j++) {
        *(float2*)(outb + (size_t)(ob + j) * MK + 2 * lane) = make_float2(a[j][0], a[j][1]);
        ss[j] = a[j][0] + a[j][1];
        qq[j] = a[j][0] * a[j][0] + a[j][1] * a[j][1];
    }
    #pragma unroll
    for (int o = 16; o; o >>= 1)
        #pragma unroll
        for (int j = 0; j < 8; j++) {
            ss[j] += __shfl_down_sync(0xffffffffu, ss[j], o);
            qq[j] += __shfl_down_sync(0xffffffffu, qq[j], o);
        }
    if (lane == 0)
        #pragma unroll
        for (int j = 0; j < 8; j++) { sS[ob + j] = ss[j]; sQ[ob + j] = qq[j]; }
    __syncthreads();
    if (tid < 64) { atomicAdd(&g_sum[tid], sS[tid]); atomicAdd(&g_sq[tid], sQ[tid]); }
    finalize_block(64, 1.0f / 524288.0f, 0, NB * M1, tid, 256);
}

// ---- convC: lanes=points, regs=channel pairs (f32x2). 32 ch x 32 pts per warp ----
template <int CIN, int COUT, int MM, int DO_MAX>
__global__ __launch_bounds__(256) void convC(const float* __restrict__ in,
                                             const float* __restrict__ wtg,
                                             float* __restrict__ out,
                                             int normStart, int slotIn, int slotOut,
                                             float invN, int wst, int chOffW,
                                             int outC, int outChOff,
                                             int finCout, int gridTotal) {
    constexpr int NW_CH = COUT / 32;
    constexpr int NW_PT = 8 / NW_CH;
    constexpr int PT = 32 * NW_PT;
    constexpr int OP = COUT / 2 + 1;
    constexpr int XS = (CIN * PT > PT * OP * 2) ? CIN * PT : PT * OP * 2;
    constexpr int NPQ = MM * 64;
    constexpr int NQ = 256 / COUT;
    constexpr int PPS = PT / NQ;
    extern __shared__ float sm[];
    float* s_x = sm;
    ull* sWp = (ull*)(sm + XS);
    float* sRed = (float*)(sWp + CIN * (COUT / 2));
    float* sNm = sRed + 768;
    float* sRs = sNm + CIN;
    ull* sOu = (ull*)sm;
    int tid = threadIdx.x, lane = tid & 31, w = tid >> 5;
    int g = w % NW_CH, pg = w / NW_CH;
    int p0g = blockIdx.x * PT;
    int b = p0g / NPQ, q0 = p0g - b * NPQ;

    for (int c = tid; c < CIN; c += 256) {
        float mn = 0.0f, rs = 0.0f;
        if (c >= normStart) { mn = g_meanL[slotIn][c - normStart]; rs = g_rstdL[slotIn][c - normStart]; }
        sNm[c] = mn; sRs[c] = rs;
    }
    __syncthreads();
    const float* inb = in + (size_t)b * CIN * NPQ + q0;
    for (int i = tid; i < CIN * PT; i += 256) {
        int c = i / PT, p = i - c * PT;
        float v = inb[(size_t)c * NPQ + p];
        if (c >= normStart) v = fmaxf((v - sNm[c]) * sRs[c], 0.0f);
        s_x[i] = v;
    }
    for (int i = tid; i < CIN * (COUT / 2); i += 256) {
        int c = i / (COUT / 2), o2 = i - c * (COUT / 2);
        sWp[i] = ((const ull*)(wtg + (size_t)c * wst + chOffW))[o2];
    }
    __syncthreads();

    ull acc[16];
    #pragma unroll
    for (int j = 0; j < 16; j++) acc[j] = 0ull;
    const float* xr = s_x + pg * 32 + lane;
    #pragma unroll 4
    for (int c = 0; c < CIN; c++) {
        float xv = xr[c * PT];
        ull xd; PACKF2(xd, xv, xv);
        const ulonglong2* wc = (const ulonglong2*)(sWp + (size_t)c * (COUT / 2) + g * 16);
        ulonglong2 w0 = wc[0], w1 = wc[1], w2 = wc[2], w3 = wc[3];
        FFMA2(acc[0], w0.x, xd); FFMA2(acc[1], w0.y, xd);
        FFMA2(acc[2], w1.x, xd); FFMA2(acc[3], w1.y, xd);
        FFMA2(acc[4], w2.x, xd); FFMA2(acc[5], w2.y, xd);
        FFMA2(acc[6], w3.x, xd); FFMA2(acc[7], w3.y, xd);
        ulonglong2 w4 = wc[4], w5 = wc[5], w6 = wc[6], w7 = wc[7];
        FFMA2(acc[8],  w4.x, xd); FFMA2(acc[9],  w4.y, xd);
        FFMA2(acc[10], w5.x, xd); FFMA2(acc[11], w5.y, xd);
        FFMA2(acc[12], w6.x, xd); FFMA2(acc[13], w6.y, xd);
        FFMA2(acc[14], w7.x, xd); FFMA2(acc[15], w7.y, xd);
    }
    __syncthreads();
    {
        size_t prow = (size_t)(pg * 32 + lane) * OP + g * 16;
        #pragma unroll
        for (int j = 0; j < 16; j++) sOu[prow + j] = acc[j];
    }
    __syncthreads();
    {
        int o = tid % COUT, qr = tid / COUT;
        const float* col = (const float*)sOu;
        float s = 0.0f, q = 0.0f, mx = -1e30f;
        int pbase = qr * PPS;
        for (int p = 0; p < PPS; p++) {
            float v = col[(size_t)(pbase + p) * (OP * 2) + o];
            s += v; q += v * v; mx = fmaxf(mx, v);
        }
        sRed[o * NQ + qr] = s;
        sRed[256 + o * NQ + qr] = q;
        sRed[512 + o * NQ + qr] = mx;
    }
    __syncthreads();
    if (tid < COUT) {
        float s = 0.0f, q = 0.0f, mx = -1e30f;
        for (int r = 0; r < NQ; r++) {
            s += sRed[tid * NQ + r];
            q += sRed[256 + tid * NQ + r];
            mx = fmaxf(mx, sRed[512 + tid * NQ + r]);
        }
        atomicAdd(&g_sum[chOffW + tid], s);
        atomicAdd(&g_sq[chOffW + tid], q);
        if (DO_MAX)
            out[((size_t)b * outC + outChOff + tid) * MM + (q0 >> 6)] = mx;
    }
    if (!DO_MAX) {
        const float* sOf = (const float*)sOu;
        for (int i = tid; i < COUT * PT; i += 256) {
            int o = i / PT, p = i - o * PT;
            out[((size_t)b * COUT + o) * NPQ + q0 + p] = sOf[(size_t)p * (OP * 2) + o];
        }
    }
    finalize_block(finCout, invN, slotOut, gridTotal, tid, 256);
}

__global__ __launch_bounds__(128) void bx2_k() {
    int bm = blockIdx.x, b = bm >> 5, m = bm & 31, tid = threadIdx.x;
    __shared__ int sn[64]; __shared__ float sc2[3];
    if (tid < 64) sn[tid] = g_n2[bm * 64 + tid];
    if (tid < 3) sc2[tid] = g_c2[((size_t)b * M2 + m) * 3 + tid];
    __syncthreads();
    for (int i = tid; i < 131 * 64; i += 128) {
        int c = i >> 6, k = i & 63, n = sn[k];
        float v;
        if (c < 3) v = g_c1[((size_t)b * M1 + n) * 3 + c] - sc2[c];
        else {
            float z = g_f1[((size_t)b * 128 + (c - 3)) * M1 + n];
            v = fmaxf((z - g_meanL[2][c - 3]) * g_rstdL[2][c - 3], 0.0f);
        }
        g_bufB[(((size_t)b * 131 + c) * M2 + m) * 64 + k] = v;
    }
}

__global__ __launch_bounds__(256) void conv1_k(const float* __restrict__ in,
                                               const float* __restrict__ wt,
                                               float* __restrict__ out,
                                               int Cin, int Cout,
                                               int normStart, int slotIn,
                                               int slotOut, float invN) {
    extern __shared__ float s_in[];
    int nOc = Cout >> 7;
    int b = blockIdx.x / nOc, oc = blockIdx.x - b * nOc;
    int tid = threadIdx.x, lane = tid & 31, wp = tid >> 5;
    const float* inb = in + (size_t)b * Cin * 32;
    for (int i = tid; i < Cin * 32; i += 256) {
        int c = i >> 5;
        float v = inb[i];
        if (c >= normStart) v = fmaxf((v - g_meanL[slotIn][c - normStart]) * g_rstdL[slotIn][c - normStart], 0.0f);
        s_in[i] = v;
    }
    __syncthreads();
    float* outb = out + (size_t)b * Cout * 32;
    for (int ob = oc * 128 + wp * 8; ob < oc * 128 + 128; ob += 64) {
        float a[8];
        #pragma unroll
        for (int j = 0; j < 8; j++) a[j] = 0.0f;
        const float4* wp4 = (const float4*)(wt + ob);
        int cstep = Cout >> 2;
        #pragma unroll 4
        for (int c = 0; c < Cin; c++) {
            float x = s_in[(c << 5) + lane];
            float4 w0 = wp4[c * cstep];
            float4 w1 = wp4[c * cstep + 1];
            a[0] += w0.x * x; a[1] += w0.y * x; a[2] += w0.z * x; a[3] += w0.w * x;
            a[4] += w1.x * x; a[5] += w1.y * x; a[6] += w1.z * x; a[7] += w1.w * x;
        }
        float qq[8];
        #pragma unroll
        for (int j = 0; j < 8; j++) {
            outb[(ob + j) * 32 + lane] = a[j];
            qq[j] = a[j] * a[j];
        }
        #pragma unroll
        for (int o = 16; o; o >>= 1)
            #pragma unroll
            for (int j = 0; j < 8; j++) {
                a[j] += __shfl_down_sync(0xffffffffu, a[j], o);
                qq[j] += __shfl_down_sync(0xffffffffu, qq[j], o);
            }
        if (lane == 0)
            #pragma unroll
            for (int j = 0; j < 8; j++) {
                atomicAdd(&g_sum[ob + j], a[j]); atomicAdd(&g_sq[ob + j], qq[j]);
            }
    }
    finalize_block(Cout, invN, slotOut, NB * nOc, tid, 256);
}

__global__ void cc2_k() {
    int b = blockIdx.x, t = threadIdx.x;
    if (t < 96) {
        int c = t / 32, m = t % 32;
        g_x3[((size_t)(b * 259 + c)) * 32 + m] = g_c2[((size_t)b * 32 + m) * 3 + c];
    }
}

__global__ void mp3_k(const float* __restrict__ in, const float* __restrict__ oneh) {
    int b = blockIdx.x, o = threadIdx.x;
    const float* p = in + ((size_t)b * 512 + o) * 32;
    float v = p[0];
    #pragma unroll
    for (int m = 1; m < 32; m++) v = fmaxf(v, p[m]);
    g_xc[o * 64 + b] = fmaxf((v - g_meanL[8][o]) * g_rstdL[8][o], 0.0f);
    if (o < 3) g_xc[(512 + o) * 64 + b] = oneh[b * 3 + o];
}

__global__ void fc_k(const float* __restrict__ x, const float* __restrict__ w,
                     float* __restrict__ out, int Cin) {
    __shared__ float sm2[2], sqv[2];
    int o = blockIdx.x, b = threadIdx.x;
    const float* wr = w + (size_t)o * Cin;
    float z = 0.0f;
    for (int c = 0; c < Cin; c++) z += x[c * 64 + b] * wr[c];
    float s = z, q = z * z;
    #pragma unroll
    for (int off = 16; off; off >>= 1) {
        s += __shfl_down_sync(0xffffffffu, s, off);
        q += __shfl_down_sync(0xffffffffu, q, off);
    }
    if ((b & 31) == 0) { sm2[b >> 5] = s; sqv[b >> 5] = q; }
    __syncthreads();
    float mn = (sm2[0] + sm2[1]) * (1.0f / 64.0f);
    float vq = (sqv[0] + sqv[1]) * (1.0f / 64.0f);
    out[o * 64 + b] = fmaxf((z - mn) * rsqrtf(vq - mn * mn + 1e-5f), 0.0f);
}

__global__ void fco_k(const float* __restrict__ x, const float* __restrict__ w,
                      const float* __restrict__ bias, float* __restrict__ out) {
    int o = blockIdx.x, b = threadIdx.x;
    const float* wr = w + (size_t)o * 256;
    float z = bias[o];
    for (int c = 0; c < 256; c++) z += x[c * 64 + b] * wr[c];
    out[b * 59 + o] = z;
}

static inline int smC(int CIN, int COUT) {
    int NW_CH = COUT / 32, PT = 32 * (8 / NW_CH), OP = COUT / 2 + 1;
    int XS = (CIN * PT > PT * OP * 2) ? CIN * PT : PT * OP * 2;
    return XS * 4 + CIN * (COUT / 2) * 8 + 768 * 4 + 2 * CIN * 4;
}

extern "C" void kernel_launch(void* const* d_in, const int* in_sizes, int n_in,
                              void* d_out, int out_size) {
    const float* coords = (const float*)d_in[0];
    const float* oneh   = (const float*)d_in[1];

    float *bufA, *bufB, *wt, *f1, *x3, *z3a, *z3b, *xc, *fa1, *fa2;
    cudaGetSymbolAddress((void**)&bufA, g_bufA);
    cudaGetSymbolAddress((void**)&bufB, g_bufB);
    cudaGetSymbolAddress((void**)&wt, g_wt);
    cudaGetSymbolAddress((void**)&f1, g_f1);
    cudaGetSymbolAddress((void**)&x3, g_x3);
    cudaGetSymbolAddress((void**)&z3a, g_z3a);
    cudaGetSymbolAddress((void**)&z3b, g_z3b);
    cudaGetSymbolAddress((void**)&xc, g_xc);
    cudaGetSymbolAddress((void**)&fa1, g_fa1);
    cudaGetSymbolAddress((void**)&fa2, g_fa2);

    const int sm6464   = smC(64, 64);
    const int sm64128  = smC(64, 128);
    const int sm131128 = smC(131, 128);
    const int sm128128 = smC(128, 128);
    cudaFuncSetAttribute(convC<64, 64, M1, 0>, cudaFuncAttributeMaxDynamicSharedMemorySize, sm6464);
    cudaFuncSetAttribute(convC<64, 128, M1, 1>, cudaFuncAttributeMaxDynamicSharedMemorySize, sm64128);
    cudaFuncSetAttribute(convC<131, 128, M2, 0>, cudaFuncAttributeMaxDynamicSharedMemorySize, sm131128);
    cudaFuncSetAttribute(convC<128, 128, M2, 0>, cudaFuncAttributeMaxDynamicSharedMemorySize, sm128128);
    cudaFuncSetAttribute(convC<128, 128, M2, 1>, cudaFuncAttributeMaxDynamicSharedMemorySize, sm128128);

    // 0: fused fps+ballquery stage 1
    fpsbq1_k<<<NB, 1024>>>(coords);
    // 1: weight transposes
    tw_all<<<256, 256>>>((const float*)d_in[2], (const float*)d_in[3], (const float*)d_in[4],
                         (const float*)d_in[5], (const float*)d_in[6], (const float*)d_in[7],
                         (const float*)d_in[8], (const float*)d_in[9], (const float*)d_in[10]);
    // 2: gather + 3->64 conv (slot0)
    convA_k<<<NB * M1, 256>>>(coords, (const float*)d_in[2]);
    // 3: 64->64 conv (slot1)  [ncu target]
    convC<64, 64, M1, 0><<<4096, 256, sm6464>>>(bufA, wt + 192, bufB,
        0, 0, 1, 1.0f / 524288.0f, 64, 0, 0, 0, 64, 4096);
    // 4: 64->128 conv + fused maxpool -> f1 (slot2)
    convC<64, 128, M1, 1><<<8192, 256, sm64128>>>(bufB, wt + 4288, f1,
        0, 1, 2, 1.0f / 524288.0f, 128, 0, 128, 0, 128, 8192);
    // 5-6: stage-2 sampling + input build
    fpsbq2_k<<<NB, 128>>>();
    bx2_k<<<NB * M2, 128>>>();
    // 7: 131->128 (no norm, slot3)
    convC<131, 128, M2, 0><<<2048, 256, sm131128>>>(bufB, wt + 12480, bufA,
        131, 0, 3, 1.0f / 131072.0f, 128, 0, 0, 0, 128, 2048);
    // 8: 128->128 (slot4)
    convC<128, 128, M2, 0><<<2048, 256, sm128128>>>(bufA, wt + 29248, bufB,
        0, 3, 4, 1.0f / 131072.0f, 128, 0, 0, 0, 128, 2048);
    // 9-10: 128->256 fused-max as two 128-wide halves -> x3 (slot5)
    convC<128, 128, M2, 1><<<2048, 256, sm128128>>>(bufB, wt + 45632, x3,
        0, 4, 5, 1.0f / 131072.0f, 256, 0, 259, 3, 256, 4096);
    convC<128, 128, M2, 1><<<2048, 256, sm128128>>>(bufB, wt + 45632, x3,
        0, 4, 5, 1.0f / 131072.0f, 256, 128, 259, 131, 256, 4096);
    // 11: centers into x3 channels 0-2
    cc2_k<<<NB, 96>>>();
    // 12-14: stage-3 convs
    conv1_k<<<NB * 2, 256, 259 * 32 * 4>>>(x3, wt + 78400, z3b, 259, 256, 3, 5, 6, 1.0f / 2048.0f);
    conv1_k<<<NB * 2, 256, 256 * 32 * 4>>>(z3b, wt + 144704, z3a, 256, 256, 0, 6, 7, 1.0f / 2048.0f);
    conv1_k<<<NB * 4, 256, 256 * 32 * 4>>>(z3a, wt + 210240, bufA, 256, 512, 0, 7, 8, 1.0f / 2048.0f);
    // 15: global max + onehot
    mp3_k<<<NB, 512>>>(bufA, oneh);
    // 16-18: FC head
    fc_k<<<512, 64>>>(xc, (const float*)d_in[11], fa1, 515);
    fc_k<<<256, 64>>>(fa1, (const float*)d_in[12], fa2, 512);
    fco_k<<<59, 64>>>(fa2, (const float*)d_in[13], (const float*)d_in[14], (float*)d_out);
}